// round 5
// baseline (speedup 1.0000x reference)
#include <cuda_runtime.h>
#include <cuda_bf16.h>
#include <cstdint>

#define D 128
#define NA 100000
#define NB 150000
#define NG 2000
#define NTOT (NA + NB + NG)      // 252000
#define DEG_TOT 756000           // sum over rels of n_dst (= sum of n_src)
#define NE_TOT 1352000           // total edges over 9 relations
#define NTILES 5910              // sum over rels of ceil(ndst/128)
#define BN_EPS 1e-5f
#define SCAN_NB ((DEG_TOT + 1023) / 1024)   // 739

// boundary tables (compile-time)
#define DOFF_INIT {0,150000,250000,252000,352000,354000,504000,604000,754000,756000}
#define SOFF_INIT {0,100000,250000,350000,352000,502000,504000,604000,754000,756000}
#define EOFF_INIT {0,300000,600000,700000,800000,950000,1100000,1200000,1350000,1352000}
#define TBASE_INIT {0,1172,1954,1970,2752,2768,3940,4722,5894,5910}
#define ST_INIT {0,1,0,2,1,2,0,1,2}

// ---------------- device scratch ----------------
__device__ int g_odeg[DEG_TOT];
__device__ int g_ideg[DEG_TOT];
__device__ int g_offs[DEG_TOT];                   // CSR offsets (global over rels)
__device__ int g_cursor[DEG_TOT];
__device__ int g_bsum[SCAN_NB];
__device__ int g_eidx[NE_TOT];                    // CSR: rel-local src index
__device__ float g_ew[NE_TOT];                    // CSR: ns[src]
__device__ float g_ns[DEG_TOT];
__device__ float g_nd[DEG_TOT];
__device__ __align__(128) __nv_bfloat16 g_mh[(size_t)NTILES * 16384];  // A tiles hi (swizzled)
__device__ __align__(128) __nv_bfloat16 g_ml[(size_t)NTILES * 16384];  // A tiles lo
__device__ float g_gout[(size_t)DEG_TOT * D];     // gemm output (pre-BN), rel dst-major
__device__ float g_feat[(size_t)NTOT * D];        // layer-0 output
__device__ float g_stats[9 * 2 * D];
__device__ float g_scale[9 * D];
__device__ float g_shift[9 * D];
__device__ __align__(128) __nv_bfloat16 g_wh[18 * D * D];  // W hi, swizzled B-tile layout
__device__ __align__(128) __nv_bfloat16 g_wl[18 * D * D];  // W lo

__device__ const int d_ndst[9] = {NB, NA, NG, NA, NG, NB, NA, NB, NG};

struct EdgePtrs { const int* s[9]; const int* d[9]; };
struct FeatPtrs { const float* f[3]; };
struct Resid4 { const float4* f[3]; };

// ---------------- helpers ----------------
__device__ __forceinline__ uint32_t sw128(uint32_t o) { return o ^ ((o >> 3) & 0x70); }
// 128x128 bf16 tile: two [128 x 64] half-tiles of 16KB, 128B swizzled rows
__device__ __forceinline__ uint32_t toff128(uint32_t row, uint32_t k) {
    return ((k >> 6) << 14) + sw128(row * 128 + ((k & 63) << 1));
}
__device__ __forceinline__ uint32_t smem_u32(const void* p) {
    uint32_t a;
    asm("{ .reg .u64 t; cvta.to.shared.u64 t, %1; cvt.u32.u64 %0, t; }" : "=r"(a) : "l"(p));
    return a;
}
__device__ __forceinline__ void ldsm4(uint32_t& r0, uint32_t& r1, uint32_t& r2, uint32_t& r3,
                                      uint32_t addr) {
    asm volatile("ldmatrix.sync.aligned.m8n8.x4.shared.b16 {%0,%1,%2,%3}, [%4];"
                 : "=r"(r0), "=r"(r1), "=r"(r2), "=r"(r3) : "r"(addr));
}
__device__ __forceinline__ void mma_bf16(float* d, const uint32_t* a, uint32_t b0, uint32_t b1) {
    asm volatile(
        "mma.sync.aligned.m16n8k16.row.col.f32.bf16.bf16.f32 "
        "{%0,%1,%2,%3}, {%4,%5,%6,%7}, {%8,%9}, {%0,%1,%2,%3};"
        : "+f"(d[0]), "+f"(d[1]), "+f"(d[2]), "+f"(d[3])
        : "r"(a[0]), "r"(a[1]), "r"(a[2]), "r"(a[3]), "r"(b0), "r"(b1));
}
__device__ __forceinline__ void cpasync16(uint32_t dst, const void* src) {
    asm volatile("cp.async.ca.shared.global [%0], [%1], 16;" :: "r"(dst), "l"(src));
}
__device__ __forceinline__ __nv_bfloat162 pack_hi(float a, float b) {
    __nv_bfloat162 r; r.x = __float2bfloat16(a); r.y = __float2bfloat16(b); return r;
}

// ---------------- setup kernels ----------------
__global__ void k_zero3(int4* a, int4* b, int4* c, int n4) {
    int i = blockIdx.x * blockDim.x + threadIdx.x;
    if (i < n4) {
        int4 z = make_int4(0, 0, 0, 0);
        a[i] = z; b[i] = z; c[i] = z;
    }
}

__global__ void k_counti_all(EdgePtrs E, int* __restrict__ od, int* __restrict__ id) {
    const int eoff[10] = EOFF_INIT;
    const int soff[10] = SOFF_INIT;
    const int doff[10] = DOFF_INIT;
    int e = blockIdx.x * blockDim.x + threadIdx.x;
    if (e >= NE_TOT) return;
    int rel = 0;
#pragma unroll
    for (int r = 1; r < 9; r++) if (e >= eoff[r]) rel = r;
    int le = e - eoff[rel];
    atomicAdd(&od[soff[rel] + E.s[rel][le]], 1);
    atomicAdd(&id[doff[rel] + E.d[rel][le]], 1);
}

// block-local exclusive scan of ideg + block sums; also computes ns, nd
__global__ void k_scan1(const int* __restrict__ ideg, const int* __restrict__ odeg,
                        int* __restrict__ out, int* __restrict__ bsum,
                        float* __restrict__ ns, float* __restrict__ nd, int n) {
    __shared__ int sh[1024];
    int gid = blockIdx.x * 1024 + threadIdx.x;
    int v = (gid < n) ? ideg[gid] : 0;
    if (gid < n) {
        int od = odeg[gid];
        ns[gid] = (od > 0) ? rsqrtf((float)od) : 0.f;
        nd[gid] = (v > 0) ? rsqrtf((float)v) : 0.f;
    }
    sh[threadIdx.x] = v;
    __syncthreads();
#pragma unroll
    for (int s = 1; s < 1024; s <<= 1) {
        int t = (threadIdx.x >= s) ? sh[threadIdx.x - s] : 0;
        __syncthreads();
        sh[threadIdx.x] += t;
        __syncthreads();
    }
    if (gid < n) out[gid] = sh[threadIdx.x] - v;
    if (threadIdx.x == 1023) bsum[blockIdx.x] = sh[1023];
}

// each block computes prefix of bsum itself and adds
__global__ void k_scan3(int* __restrict__ out, const int* __restrict__ bsum, int n) {
    int b = blockIdx.x;
    int partial = 0;
    for (int j = threadIdx.x; j < b; j += 1024) partial += bsum[j];
#pragma unroll
    for (int s = 16; s >= 1; s >>= 1) partial += __shfl_down_sync(0xffffffffu, partial, s);
    __shared__ int ws[32];
    __shared__ int tot;
    if (threadIdx.x == 0) tot = 0;
    __syncthreads();
    if ((threadIdx.x & 31) == 0) atomicAdd(&tot, partial);
    __syncthreads();
    (void)ws;
    int gid = b * 1024 + threadIdx.x;
    if (gid < n) out[gid] += tot;
}

__global__ void k_fill_all(EdgePtrs E, const float* __restrict__ ns,
                           const int* __restrict__ offs, int* __restrict__ cur) {
    const int eoff[10] = EOFF_INIT;
    const int soff[10] = SOFF_INIT;
    const int doff[10] = DOFF_INIT;
    int e = blockIdx.x * blockDim.x + threadIdx.x;
    if (e >= NE_TOT) return;
    int rel = 0;
#pragma unroll
    for (int r = 1; r < 9; r++) if (e >= eoff[r]) rel = r;
    int le = e - eoff[rel];
    int ss = E.s[rel][le];
    int dd = E.d[rel][le];
    int gslot = doff[rel] + dd;
    int pos = offs[gslot] + atomicAdd(&cur[gslot], 1);
    g_eidx[pos] = ss;
    g_ew[pos] = ns[soff[rel] + ss];
}

// split W (fp32 [18][k][n]) into bf16 hi/lo stored as B tile [n][k], swizzled
__global__ void k_wsplit(const float* __restrict__ W) {
    int rel = blockIdx.x;  // 0..17
    const float* w = W + (size_t)rel * D * D;
    char* wh = (char*)g_wh + (size_t)rel * D * D * 2;
    char* wl = (char*)g_wl + (size_t)rel * D * D * 2;
    for (int idx = threadIdx.x; idx < D * D; idx += blockDim.x) {
        int k = idx >> 7, n = idx & 127;
        float x = w[idx];
        __nv_bfloat16 h = __float2bfloat16(x);
        __nv_bfloat16 l = __float2bfloat16(x - __bfloat162float(h));
        uint32_t off = toff128(n, k);
        *(__nv_bfloat16*)(wh + off) = h;
        *(__nv_bfloat16*)(wl + off) = l;
    }
}

// ---------------- batched gather ----------------
// one warp per global dst slot; m_row = nd * sum_e feat[eidx]*ew, written as bf16 hi/lo
// directly into the swizzled GEMM A-tile layout. Block 0 also zeroes g_stats.
__global__ void k_gather_all(FeatPtrs F, const int* __restrict__ offs,
                             const int* __restrict__ ideg, const int* __restrict__ eidx,
                             const float* __restrict__ ew, const float* __restrict__ nd) {
    const int doff[10] = DOFF_INIT;
    const int tbase[10] = TBASE_INIT;
    const int st[9] = ST_INIT;
    if (blockIdx.x == 0) {
        for (int i = threadIdx.x; i < 9 * 256; i += blockDim.x) g_stats[i] = 0.f;
    }
    int row = blockIdx.x * (blockDim.x >> 5) + (threadIdx.x >> 5);
    int lane = threadIdx.x & 31;
    if (row >= DEG_TOT) return;
    int rel = 0;
#pragma unroll
    for (int r = 1; r < 9; r++) if (row >= doff[r]) rel = r;
    int lrow = row - doff[rel];
    const float* feat = F.f[st[rel]];

    int o = offs[row];
    int dg = ideg[row];
    float4 acc = make_float4(0.f, 0.f, 0.f, 0.f);
    int e = 0;
    for (; e + 2 <= dg; e += 2) {
        int s0 = __ldg(eidx + o + e);
        int s1 = __ldg(eidx + o + e + 1);
        float w0 = __ldg(ew + o + e);
        float w1 = __ldg(ew + o + e + 1);
        float4 v0 = __ldg((const float4*)(feat + (size_t)s0 * D + lane * 4));
        float4 v1 = __ldg((const float4*)(feat + (size_t)s1 * D + lane * 4));
        acc.x += v0.x * w0 + v1.x * w1;
        acc.y += v0.y * w0 + v1.y * w1;
        acc.z += v0.z * w0 + v1.z * w1;
        acc.w += v0.w * w0 + v1.w * w1;
    }
    if (e < dg) {
        int s0 = __ldg(eidx + o + e);
        float w0 = __ldg(ew + o + e);
        float4 v0 = __ldg((const float4*)(feat + (size_t)s0 * D + lane * 4));
        acc.x += v0.x * w0;
        acc.y += v0.y * w0;
        acc.z += v0.z * w0;
        acc.w += v0.w * w0;
    }
    float ndv = __ldg(nd + row);
    acc.x *= ndv; acc.y *= ndv; acc.z *= ndv; acc.w *= ndv;

    // hi/lo split
    __nv_bfloat162 h0 = pack_hi(acc.x, acc.y);
    __nv_bfloat162 h1 = pack_hi(acc.z, acc.w);
    __nv_bfloat162 l0 = pack_hi(acc.x - __bfloat162float(h0.x), acc.y - __bfloat162float(h0.y));
    __nv_bfloat162 l1 = pack_hi(acc.z - __bfloat162float(h1.x), acc.w - __bfloat162float(h1.y));

    size_t tile = (size_t)tbase[rel] + (lrow >> 7);
    int ir = lrow & 127;
    char* bh = (char*)g_mh + tile * 32768;
    char* bl = (char*)g_ml + tile * 32768;
    uint32_t o0 = toff128(ir, lane * 4);
    uint32_t o1 = toff128(ir, lane * 4 + 2);
    *(__nv_bfloat162*)(bh + o0) = h0;
    *(__nv_bfloat162*)(bh + o1) = h1;
    *(__nv_bfloat162*)(bl + o0) = l0;
    *(__nv_bfloat162*)(bl + o1) = l1;
}

// ---------------- batched GEMM + stats epilogue ----------------
#define OFF_AHI  0
#define OFF_ALO  32768
#define OFF_BHI  65536
#define OFF_BLO  98304
#define OFF_STAT 131072
#define SMEM_DYN (131072 + 1024 + 1024)

__global__ __launch_bounds__(256, 1)
void k_gemm_all(const __nv_bfloat16* __restrict__ mh, const __nv_bfloat16* __restrict__ ml,
                const __nv_bfloat16* __restrict__ whAll, const __nv_bfloat16* __restrict__ wlAll,
                int layer, float* __restrict__ out, float* __restrict__ stats) {
    const int tbase[10] = TBASE_INIT;
    const int doff[10] = DOFF_INIT;
    extern __shared__ char smem_raw[];
    char* smem = (char*)((((uintptr_t)smem_raw) + 1023) & ~(uintptr_t)1023);
    uint32_t sa = smem_u32(smem);
    int tid = threadIdx.x;
    int lane = tid & 31;
    int wid = tid >> 5;
    int bid = blockIdx.x;

    int rel = 0;
#pragma unroll
    for (int r = 1; r < 9; r++) if (bid >= tbase[r]) rel = r;
    int rowBase = (bid - tbase[rel]) * 128;
    int ndst = doff[rel + 1] - doff[rel];
    int goutBase = doff[rel];

    ((float*)(smem + OFF_STAT))[tid] = 0.f;

    // async copy: A hi/lo tile (this CTA's) + B hi/lo (rel's W)
    {
        const char* sAh = (const char*)mh + (size_t)bid * 32768;
        const char* sAl = (const char*)ml + (size_t)bid * 32768;
        int lr = layer * 9 + rel;
        const char* sBh = (const char*)whAll + (size_t)lr * 32768;
        const char* sBl = (const char*)wlAll + (size_t)lr * 32768;
#pragma unroll
        for (int i = tid; i < 2048; i += 256) {
            cpasync16(sa + OFF_AHI + i * 16, sAh + i * 16);
            cpasync16(sa + OFF_ALO + i * 16, sAl + i * 16);
            cpasync16(sa + OFF_BHI + i * 16, sBh + i * 16);
            cpasync16(sa + OFF_BLO + i * 16, sBl + i * 16);
        }
        asm volatile("cp.async.commit_group;" ::: "memory");
        asm volatile("cp.async.wait_group 0;" ::: "memory");
    }
    __syncthreads();

    float acc[16][4];
#pragma unroll
    for (int t = 0; t < 16; t++)
#pragma unroll
        for (int j = 0; j < 4; j++) acc[t][j] = 0.f;

    int m0 = wid * 16;
    uint32_t rowA = m0 + (lane & 15);
    uint32_t kA = (lane >> 4) << 3;
    uint32_t rowB = (lane & 7) + ((lane >> 4) << 3);
    uint32_t kB = ((lane >> 3) & 1) << 3;

    const uint32_t abase[3] = {sa + OFF_AHI, sa + OFF_AHI, sa + OFF_ALO};
    const uint32_t bbase[3] = {sa + OFF_BHI, sa + OFF_BLO, sa + OFF_BHI};

#pragma unroll
    for (int s = 0; s < 3; s++) {
        uint32_t ab = abase[s];
        uint32_t bb = bbase[s];
#pragma unroll
        for (int k0 = 0; k0 < 128; k0 += 16) {
            uint32_t a[4];
            ldsm4(a[0], a[1], a[2], a[3], ab + toff128(rowA, k0 + kA));
#pragma unroll
            for (int nn = 0; nn < 8; nn++) {
                uint32_t b0, b1, b2, b3;
                ldsm4(b0, b1, b2, b3, bb + toff128(nn * 16 + rowB, k0 + kB));
                mma_bf16(acc[2 * nn], a, b0, b1);
                mma_bf16(acc[2 * nn + 1], a, b2, b3);
            }
        }
    }

    // epilogue (nd/bias pre-folded): write gout + column stats
    int quad = lane >> 2;
    int cp = (lane & 3) * 2;
    int lr0 = rowBase + m0 + quad;
    int lr1 = lr0 + 8;
    bool v0 = lr0 < ndst, v1 = lr1 < ndst;
    float* sstat = (float*)(smem + OFF_STAT);

#pragma unroll
    for (int t = 0; t < 16; t++) {
        int c = t * 8 + cp;
        float x0 = acc[t][0], x1 = acc[t][1];
        float y0 = acc[t][2], y1 = acc[t][3];
        if (v0) *(float2*)(out + (size_t)(goutBase + lr0) * D + c) = make_float2(x0, x1);
        if (v1) *(float2*)(out + (size_t)(goutBase + lr1) * D + c) = make_float2(y0, y1);
        float s0 = (v0 ? x0 : 0.f) + (v1 ? y0 : 0.f);
        float s1 = (v0 ? x1 : 0.f) + (v1 ? y1 : 0.f);
        float q0 = (v0 ? x0 * x0 : 0.f) + (v1 ? y0 * y0 : 0.f);
        float q1 = (v0 ? x1 * x1 : 0.f) + (v1 ? y1 * y1 : 0.f);
#pragma unroll
        for (int S = 4; S <= 16; S <<= 1) {
            s0 += __shfl_xor_sync(0xffffffffu, s0, S);
            s1 += __shfl_xor_sync(0xffffffffu, s1, S);
            q0 += __shfl_xor_sync(0xffffffffu, q0, S);
            q1 += __shfl_xor_sync(0xffffffffu, q1, S);
        }
        if (lane < 4) {
            atomicAdd(&sstat[c], s0);
            atomicAdd(&sstat[c + 1], s1);
            atomicAdd(&sstat[128 + c], q0);
            atomicAdd(&sstat[128 + c + 1], q1);
        }
    }
    __syncthreads();
    atomicAdd(&stats[rel * 256 + tid], sstat[tid]);
}

// per-rel BN scale/shift from stats
__global__ void k_finalize9(const float* __restrict__ gammaL, const float* __restrict__ betaL) {
    int r = blockIdx.x;
    int c = threadIdx.x;
    float n = (float)d_ndst[r];
    float mu = g_stats[r * 256 + c] / n;
    float var = g_stats[r * 256 + 128 + c] / n - mu * mu;
    float inv = rsqrtf(var + BN_EPS);
    float sc = inv * gammaL[r * D + c];
    g_scale[r * D + c] = sc;
    g_shift[r * D + c] = betaL[r * D + c] - mu * sc;
}

// batched fused normalize + 3-rel sum (+ residual on layer 1)
__global__ void k_fuse_all(const float* __restrict__ gout, Resid4 R, int layer,
                           float4* __restrict__ out) {
    const int doff[10] = DOFF_INIT;
    int i = blockIdx.x * blockDim.x + threadIdx.x;
    if (i >= NTOT * 32) return;
    int row = i >> 5;
    int c4 = i & 31;
    int c = c4 * 4;
    int type = (row < NA) ? 0 : (row < NA + NB) ? 1 : 2;
    const int toff_[3] = {0, NA, NA + NB};
    const int rl_[3][3] = {{1, 3, 6}, {0, 5, 7}, {2, 4, 8}};
    int local = row - toff_[type];
    int r0 = rl_[type][0], r1 = rl_[type][1], r2 = rl_[type][2];
    const float4* g0 = (const float4*)(gout + (size_t)(doff[r0] + local) * D);
    const float4* g1 = (const float4*)(gout + (size_t)(doff[r1] + local) * D);
    const float4* g2 = (const float4*)(gout + (size_t)(doff[r2] + local) * D);
    float4 a = g0[c4], b = g1[c4], g = g2[c4];
    float4 o;
    o.x = a.x * g_scale[r0 * D + c + 0] + b.x * g_scale[r1 * D + c + 0] + g.x * g_scale[r2 * D + c + 0]
        + g_shift[r0 * D + c + 0] + g_shift[r1 * D + c + 0] + g_shift[r2 * D + c + 0];
    o.y = a.y * g_scale[r0 * D + c + 1] + b.y * g_scale[r1 * D + c + 1] + g.y * g_scale[r2 * D + c + 1]
        + g_shift[r0 * D + c + 1] + g_shift[r1 * D + c + 1] + g_shift[r2 * D + c + 1];
    o.z = a.z * g_scale[r0 * D + c + 2] + b.z * g_scale[r1 * D + c + 2] + g.z * g_scale[r2 * D + c + 2]
        + g_shift[r0 * D + c + 2] + g_shift[r1 * D + c + 2] + g_shift[r2 * D + c + 2];
    o.w = a.w * g_scale[r0 * D + c + 3] + b.w * g_scale[r1 * D + c + 3] + g.w * g_scale[r2 * D + c + 3]
        + g_shift[r0 * D + c + 3] + g_shift[r1 * D + c + 3] + g_shift[r2 * D + c + 3];
    if (layer == 1) {
        float4 rr = R.f[type][(size_t)local * 32 + c4];
        o.x += rr.x; o.y += rr.y; o.z += rr.z; o.w += rr.w;
    }
    out[i] = o;
}

// ---------------- host orchestration ----------------
static inline int cdiv(int a, int b) { return (a + b - 1) / b; }

extern "C" void kernel_launch(void* const* d_in, const int* in_sizes, int n_in,
                              void* d_out, int out_size) {
    const float* fa = (const float*)d_in[0];
    const float* fb = (const float*)d_in[1];
    const float* fg = (const float*)d_in[2];
    const float* W = (const float*)d_in[3];
    const float* gamma = (const float*)d_in[5];
    const float* beta = (const float*)d_in[6];

    EdgePtrs E;
    for (int r = 0; r < 9; r++) {
        E.s[r] = (const int*)d_in[7 + 2 * r];
        E.d[r] = (const int*)d_in[8 + 2 * r];
    }

    int *p_odeg, *p_ideg, *p_offs, *p_cursor, *p_bsum, *p_eidx;
    float *p_ns, *p_nd, *p_gout, *p_feat, *p_stats, *p_ew;
    __nv_bfloat16 *p_wh, *p_wl, *p_mh, *p_ml;
    cudaGetSymbolAddress((void**)&p_odeg, g_odeg);
    cudaGetSymbolAddress((void**)&p_ideg, g_ideg);
    cudaGetSymbolAddress((void**)&p_offs, g_offs);
    cudaGetSymbolAddress((void**)&p_cursor, g_cursor);
    cudaGetSymbolAddress((void**)&p_bsum, g_bsum);
    cudaGetSymbolAddress((void**)&p_eidx, g_eidx);
    cudaGetSymbolAddress((void**)&p_ew, g_ew);
    cudaGetSymbolAddress((void**)&p_ns, g_ns);
    cudaGetSymbolAddress((void**)&p_nd, g_nd);
    cudaGetSymbolAddress((void**)&p_gout, g_gout);
    cudaGetSymbolAddress((void**)&p_feat, g_feat);
    cudaGetSymbolAddress((void**)&p_stats, g_stats);
    cudaGetSymbolAddress((void**)&p_wh, g_wh);
    cudaGetSymbolAddress((void**)&p_wl, g_wl);
    cudaGetSymbolAddress((void**)&p_mh, g_mh);
    cudaGetSymbolAddress((void**)&p_ml, g_ml);

    cudaFuncSetAttribute(k_gemm_all, cudaFuncAttributeMaxDynamicSharedMemorySize, SMEM_DYN);

    const int TB = 256;

    // 0: zero degree/cursor arrays
    k_zero3<<<cdiv(DEG_TOT / 4, TB), TB>>>((int4*)p_odeg, (int4*)p_ideg, (int4*)p_cursor,
                                           DEG_TOT / 4);
    // 1: batched degree count
    k_counti_all<<<cdiv(NE_TOT, TB), TB>>>(E, p_odeg, p_ideg);
    // 2: block scan (+ ns/nd)
    k_scan1<<<SCAN_NB, 1024>>>(p_ideg, p_odeg, p_offs, p_bsum, p_ns, p_nd, DEG_TOT);
    // 3: scan fixup
    k_scan3<<<SCAN_NB, 1024>>>(p_offs, p_bsum, DEG_TOT);
    // 4: batched CSR fill
    k_fill_all<<<cdiv(NE_TOT, TB), TB>>>(E, p_ns, p_offs, p_cursor);

    FeatPtrs F0; F0.f[0] = fa; F0.f[1] = fb; F0.f[2] = fg;
    FeatPtrs F1; F1.f[0] = p_feat; F1.f[1] = p_feat + (size_t)NA * D;
    F1.f[2] = p_feat + (size_t)(NA + NB) * D;
    Resid4 R; R.f[0] = (const float4*)fa; R.f[1] = (const float4*)fb; R.f[2] = (const float4*)fg;

    // 5: batched gather, layer 0  (ncu captures this launch)
    k_gather_all<<<cdiv(DEG_TOT, TB / 32), TB>>>(F0, p_offs, p_ideg, p_eidx, p_ew, p_nd);
    // 6: weight split
    k_wsplit<<<18, 256>>>(W);
    // 7: batched GEMM layer 0
    k_gemm_all<<<NTILES, 256, SMEM_DYN>>>(p_mh, p_ml, p_wh, p_wl, 0, p_gout, p_stats);
    // 8: BN finalize
    k_finalize9<<<9, 128>>>(gamma, beta);
    // 9: fused normalize+sum -> g_feat
    k_fuse_all<<<cdiv(NTOT * 32, TB), TB>>>(p_gout, R, 0, (float4*)p_feat);

    // layer 1
    k_gather_all<<<cdiv(DEG_TOT, TB / 32), TB>>>(F1, p_offs, p_ideg, p_eidx, p_ew, p_nd);
    k_gemm_all<<<NTILES, 256, SMEM_DYN>>>(p_mh, p_ml, p_wh, p_wl, 1, p_gout, p_stats);
    k_finalize9<<<9, 128>>>(gamma + 9 * D, beta + 9 * D);
    k_fuse_all<<<cdiv(NTOT * 32, TB), TB>>>(p_gout, R, 1, (float4*)d_out);
}